// round 5
// baseline (speedup 1.0000x reference)
#include <cuda_runtime.h>
#include <cuda_bf16.h>

// IF spiking neuron forward (non-align, T>0):
//   x: [T, B, 1024, 3072] fp32 (flattened T*B), thresh2/dtmem: [1024,3072]
//   mem0 = dtmem*thre; per t: mem += x_t; spike = (mem>=thre)?thre:0; mem -= spike
//
// R5: B_PER_TH=1 (R1's regs=32 / occ~80% shape, which measured 6863 GB/s) with
// the batch index in the LOW 3 bits of blockIdx.x: all 8 batch-blocks sharing
// a 256-f param range launch adjacently -> co-resident -> 7/8 param reads hit
// L2 (kills R1's ~124MB DRAM param re-fetch). Streaming hints on x/out protect
// param L2 residency.

#define T_STEPS 4
#define B_BATCH 8
#define FEAT_N  (1024u * 3072u)       // 3,145,728 feature elements
#define N4      (FEAT_N / 4u)         // 786,432 float4 per feature map

__global__ __launch_bounds__(256) void if_fwd_kernel(
    const float4* __restrict__ x,
    const float4* __restrict__ thresh,
    const float4* __restrict__ dtm,
    float4* __restrict__ out)
{
    const unsigned bid = blockIdx.x;
    const unsigned b   = bid & 7u;                          // batch index 0..7
    const unsigned f   = (bid >> 3) * 256u + threadIdx.x;   // feature float4 index
    if (f >= N4) return;

    const float4 th = __ldg(&thresh[f]);
    const float4 dm = __ldg(&dtm[f]);

    float mx = dm.x * th.x;
    float my = dm.y * th.y;
    float mz = dm.z * th.z;
    float mw = dm.w * th.w;

    const float4* __restrict__ xp = x   + (size_t)b * N4 + f;
    float4* __restrict__       op = out + (size_t)b * N4 + f;

#pragma unroll
    for (int t = 0; t < T_STEPS; ++t) {
        const float4 xv = __ldcs(xp + (size_t)t * (B_BATCH * (size_t)N4));

        mx += xv.x; my += xv.y; mz += xv.z; mw += xv.w;

        float4 sp;
        sp.x = (mx - th.x >= 0.0f) ? th.x : 0.0f;
        sp.y = (my - th.y >= 0.0f) ? th.y : 0.0f;
        sp.z = (mz - th.z >= 0.0f) ? th.z : 0.0f;
        sp.w = (mw - th.w >= 0.0f) ? th.w : 0.0f;

        mx -= sp.x; my -= sp.y; mz -= sp.z; mw -= sp.w;

        __stcs(op + (size_t)t * (B_BATCH * (size_t)N4), sp);
    }
}

extern "C" void kernel_launch(void* const* d_in, const int* in_sizes, int n_in,
                              void* d_out, int out_size)
{
    const float4* x      = (const float4*)d_in[0];
    const float4* thresh = (const float4*)d_in[1];
    const float4* dtm    = (const float4*)d_in[2];
    float4* out          = (float4*)d_out;

    const int threads = 256;
    const int blocks  = (N4 / threads) * B_BATCH;   // 24576 blocks
    if_fwd_kernel<<<blocks, threads>>>(x, thresh, dtm, out);
}

// round 6
// speedup vs baseline: 1.0439x; 1.0439x over previous
#include <cuda_runtime.h>
#include <cuda_bf16.h>

// IF spiking neuron forward (non-align, T>0):
//   x: [T, B, 1024, 3072] fp32 (flattened T*B), thresh2/dtmem: [1024,3072]
//   mem0 = dtmem*thre; per t: mem += x_t; spike = (mem>=thre)?thre:0; mem -= spike
//
// R6 = R4 (B_PER_TH=4, batch-half in low bid bit for L2 param sharing,
// streaming hints) + software pipeline over t: the 4 loads for t+1 are issued
// BEFORE computing/storing t, so each warp keeps ~4 DRAM lines in flight
// through the compute phase (R4's duty-cycle hole; governing variable is
// in-flight lines/SM, refuting the occupancy-monotone model R5 tested).

#define T_STEPS  4
#define B_BATCH  8
#define B_PER_TH 4
#define FEAT_N   (1024u * 3072u)      // 3,145,728 feature elements
#define N4       (FEAT_N / 4u)        // 786,432 float4 per feature map

__global__ __launch_bounds__(256, 4) void if_fwd_kernel(
    const float4* __restrict__ x,
    const float4* __restrict__ thresh,
    const float4* __restrict__ dtm,
    float4* __restrict__ out)
{
    const unsigned bid   = blockIdx.x;
    const unsigned f     = (bid >> 1) * 256u + threadIdx.x;   // feature float4 index
    const unsigned bbase = (bid & 1u) * B_PER_TH;             // batch half: 0..3 or 4..7
    if (f >= N4) return;

    const float4 th = __ldg(&thresh[f]);
    const float4 dm = __ldg(&dtm[f]);

    float4 mem[B_PER_TH];
#pragma unroll
    for (int b = 0; b < B_PER_TH; ++b) {
        mem[b].x = dm.x * th.x;
        mem[b].y = dm.y * th.y;
        mem[b].z = dm.z * th.z;
        mem[b].w = dm.w * th.w;
    }

    const size_t tstride = (size_t)B_BATCH * N4;
    const float4* __restrict__ xp = x   + (size_t)bbase * N4 + f;
    float4* __restrict__       op = out + (size_t)bbase * N4 + f;

    // Prologue: loads for t=0
    float4 xv[B_PER_TH];
#pragma unroll
    for (int b = 0; b < B_PER_TH; ++b)
        xv[b] = __ldcs(xp + (size_t)b * N4);

#pragma unroll
    for (int t = 0; t < T_STEPS; ++t) {
        // Prefetch t+1 before touching xv (keeps 4 loads in flight during compute)
        float4 xn[B_PER_TH];
        if (t + 1 < T_STEPS) {
            const float4* __restrict__ xq = xp + (size_t)(t + 1) * tstride;
#pragma unroll
            for (int b = 0; b < B_PER_TH; ++b)
                xn[b] = __ldcs(xq + (size_t)b * N4);
        }

        float4* __restrict__ ot = op + (size_t)t * tstride;
#pragma unroll
        for (int b = 0; b < B_PER_TH; ++b) {
            mem[b].x += xv[b].x;
            mem[b].y += xv[b].y;
            mem[b].z += xv[b].z;
            mem[b].w += xv[b].w;

            float4 sp;
            sp.x = (mem[b].x - th.x >= 0.0f) ? th.x : 0.0f;
            sp.y = (mem[b].y - th.y >= 0.0f) ? th.y : 0.0f;
            sp.z = (mem[b].z - th.z >= 0.0f) ? th.z : 0.0f;
            sp.w = (mem[b].w - th.w >= 0.0f) ? th.w : 0.0f;

            mem[b].x -= sp.x;
            mem[b].y -= sp.y;
            mem[b].z -= sp.z;
            mem[b].w -= sp.w;

            __stcs(ot + (size_t)b * N4, sp);
        }

        if (t + 1 < T_STEPS) {
#pragma unroll
            for (int b = 0; b < B_PER_TH; ++b)
                xv[b] = xn[b];
        }
    }
}

extern "C" void kernel_launch(void* const* d_in, const int* in_sizes, int n_in,
                              void* d_out, int out_size)
{
    const float4* x      = (const float4*)d_in[0];
    const float4* thresh = (const float4*)d_in[1];
    const float4* dtm    = (const float4*)d_in[2];
    float4* out          = (float4*)d_out;

    const int threads = 256;
    const int blocks  = (N4 / threads) * 2;   // 6144 blocks
    if_fwd_kernel<<<blocks, threads>>>(x, thresh, dtm, out);
}

// round 7
// speedup vs baseline: 1.0626x; 1.0179x over previous
#include <cuda_runtime.h>
#include <cuda_bf16.h>

// IF spiking neuron forward (non-align, T>0):
//   x: [T, B, 1024, 3072] fp32 (flattened T*B), thresh2/dtmem: [1024,3072]
//   mem0 = dtmem*thre; per t: mem += x_t; spike = (mem>=thre)?thre:0; mem -= spike
//
// R7: synthesis of the measured BW frontier.
//  - B_PER_TH=1, batch in LOW 3 bits of blockIdx.x -> 8 batch-blocks per
//    256-f param range co-resident -> params read ~once from DRAM (R5-verified).
//  - ALL 4 t-loads issued before any compute (explicit front-batch; the mem
//    recurrence is compute-only, so loads are address-independent). This is
//    what gave R1 its 6863 GB/s; R5's regs=26 shows the compiler otherwise
//    serializes them into the dependency chain.
//  - ~38 regs -> 6 blocks/SM -> occ ~75%: both BW conditions (>=4 batched
//    loads AND occ>=70%) hold simultaneously for the first time.

#define T_STEPS 4
#define B_BATCH 8
#define FEAT_N  (1024u * 3072u)       // 3,145,728 feature elements
#define N4      (FEAT_N / 4u)         // 786,432 float4 per feature map

__global__ __launch_bounds__(256, 6) void if_fwd_kernel(
    const float4* __restrict__ x,
    const float4* __restrict__ thresh,
    const float4* __restrict__ dtm,
    float4* __restrict__ out)
{
    const unsigned bid = blockIdx.x;
    const unsigned b   = bid & 7u;                          // batch index 0..7
    const unsigned f   = (bid >> 3) * 256u + threadIdx.x;   // feature float4 index
    if (f >= N4) return;

    const size_t tstride = (size_t)B_BATCH * N4;
    const float4* __restrict__ xp = x   + (size_t)b * N4 + f;
    float4* __restrict__       op = out + (size_t)b * N4 + f;

    // Front-batch ALL timestep loads (address-independent; only the membrane
    // recurrence is sequential, and that's pure compute).
    float4 xv0 = __ldcs(xp);
    float4 xv1 = __ldcs(xp + tstride);
    float4 xv2 = __ldcs(xp + 2 * tstride);
    float4 xv3 = __ldcs(xp + 3 * tstride);

    const float4 th = __ldg(&thresh[f]);
    const float4 dm = __ldg(&dtm[f]);

    float mx = dm.x * th.x;
    float my = dm.y * th.y;
    float mz = dm.z * th.z;
    float mw = dm.w * th.w;

    float4 sp;

    // t = 0
    mx += xv0.x; my += xv0.y; mz += xv0.z; mw += xv0.w;
    sp.x = (mx - th.x >= 0.0f) ? th.x : 0.0f;
    sp.y = (my - th.y >= 0.0f) ? th.y : 0.0f;
    sp.z = (mz - th.z >= 0.0f) ? th.z : 0.0f;
    sp.w = (mw - th.w >= 0.0f) ? th.w : 0.0f;
    mx -= sp.x; my -= sp.y; mz -= sp.z; mw -= sp.w;
    __stcs(op, sp);

    // t = 1
    mx += xv1.x; my += xv1.y; mz += xv1.z; mw += xv1.w;
    sp.x = (mx - th.x >= 0.0f) ? th.x : 0.0f;
    sp.y = (my - th.y >= 0.0f) ? th.y : 0.0f;
    sp.z = (mz - th.z >= 0.0f) ? th.z : 0.0f;
    sp.w = (mw - th.w >= 0.0f) ? th.w : 0.0f;
    mx -= sp.x; my -= sp.y; mz -= sp.z; mw -= sp.w;
    __stcs(op + tstride, sp);

    // t = 2
    mx += xv2.x; my += xv2.y; mz += xv2.z; mw += xv2.w;
    sp.x = (mx - th.x >= 0.0f) ? th.x : 0.0f;
    sp.y = (my - th.y >= 0.0f) ? th.y : 0.0f;
    sp.z = (mz - th.z >= 0.0f) ? th.z : 0.0f;
    sp.w = (mw - th.w >= 0.0f) ? th.w : 0.0f;
    mx -= sp.x; my -= sp.y; mz -= sp.z; mw -= sp.w;
    __stcs(op + 2 * tstride, sp);

    // t = 3
    mx += xv3.x; my += xv3.y; mz += xv3.z; mw += xv3.w;
    sp.x = (mx - th.x >= 0.0f) ? th.x : 0.0f;
    sp.y = (my - th.y >= 0.0f) ? th.y : 0.0f;
    sp.z = (mz - th.z >= 0.0f) ? th.z : 0.0f;
    sp.w = (mw - th.w >= 0.0f) ? th.w : 0.0f;
    mx -= sp.x; my -= sp.y; mz -= sp.z; mw -= sp.w;
    __stcs(op + 3 * tstride, sp);
}

extern "C" void kernel_launch(void* const* d_in, const int* in_sizes, int n_in,
                              void* d_out, int out_size)
{
    const float4* x      = (const float4*)d_in[0];
    const float4* thresh = (const float4*)d_in[1];
    const float4* dtm    = (const float4*)d_in[2];
    float4* out          = (float4*)d_out;

    const int threads = 256;
    const int blocks  = (N4 / threads) * B_BATCH;   // 24576 blocks
    if_fwd_kernel<<<blocks, threads>>>(x, thresh, dtm, out);
}